// round 14
// baseline (speedup 1.0000x reference)
#include <cuda_runtime.h>

#define CDIM 10000
#define CV4  2500
#define CV4PAD 2560   // 10 full iterations of 256 -> no partial-warp collectives
#define BDIM 4096
#define NT   256
#define NW   8
#define WCAP 64      // staging slots per warp
#define DCAP 384     // dense candidate cap
#define CUTF 2.0f

typedef unsigned long long ull;

__device__ __align__(16) float g_partial[BDIM];
__device__ unsigned g_done = 0;

__device__ __forceinline__ unsigned key_of(float f) {
    unsigned u = __float_as_uint(f);
    return u ^ ((unsigned)((int)u >> 31) | 0x80000000u);
}
__device__ __forceinline__ float val_of(unsigned k) {
    unsigned m = ((int)k < 0) ? 0x80000000u : 0xFFFFFFFFu;
    return __uint_as_float(k ^ m);
}

// ---- packed f32x2 helpers (FFMA2 path, PTX-only on sm_103a) ----
__device__ __forceinline__ ull pk2(float a, float b) {
    ull r; asm("mov.b64 %0, {%1, %2};" : "=l"(r) : "f"(a), "f"(b)); return r;
}
__device__ __forceinline__ void upk2f(ull p, float& a, float& b) {
    asm("mov.b64 {%0, %1}, %2;" : "=f"(a), "=f"(b) : "l"(p));
}
__device__ __forceinline__ void upk2u(ull p, unsigned& a, unsigned& b) {
    asm("mov.b64 {%0, %1}, %2;" : "=r"(a), "=r"(b) : "l"(p));
}
__device__ __forceinline__ ull fma2_(ull a, ull b, ull c) {
    ull d; asm("fma.rn.f32x2 %0, %1, %2, %3;" : "=l"(d) : "l"(a), "l"(b), "l"(c)); return d;
}
__device__ __forceinline__ ull add2_(ull a, ull b) {
    ull d; asm("add.rn.f32x2 %0, %1, %2;" : "=l"(d) : "l"(a), "l"(b)); return d;
}

// scalar exp(x), pure FFMA, deg-4 (tail uses only)
__device__ __forceinline__ float fexp_(float x) {
    const float LOG2E = 1.4426950408889634f;
    float t = fmaf(x, LOG2E, 12582912.0f);
    float f = fmaf(x, LOG2E, -(t - 12582912.0f));
    float p =          9.6181291076e-3f;
    p = fmaf(p, f, 5.5504108664e-2f);
    p = fmaf(p, f, 2.4022650695910071e-1f);
    p = fmaf(p, f, 6.9314718055994531e-1f);
    p = fmaf(p, f, 1.0f);
    return p * __uint_as_float((__float_as_uint(t) << 23) + 0x3F800000u);
}

__global__ void __launch_bounds__(NT, 6) row_kernel(
    const float* __restrict__ logit, const int* __restrict__ target,
    const float* __restrict__ lcn,   const int* __restrict__ kpc,
    float* __restrict__ out)
{
    __shared__ float    s_sv[NW * WCAP];
    __shared__ float    s_sa[NW * WCAP];
    __shared__ float    s_dv[DCAP];
    __shared__ float    s_da[DCAP];
    __shared__ float    s_red[NW];
    __shared__ unsigned s_wcnt[NW], s_base[NW];
    __shared__ float    s_Z, s_T, s_ft, s_at;
    __shared__ int      s_k, s_last, s_fast;
    __shared__ unsigned s_n, s_cnt;

    const int row  = blockIdx.x;
    const int tid  = threadIdx.x;
    const int lane = tid & 31;
    const int wid  = tid >> 5;
    const unsigned lmask = (1u << lane) - 1u;

    const float* lrow = logit + (size_t)row * CDIM;

    if (tid == NT - 1) {
        int tg = __ldg(target + row);
        int k  = __ldg(kpc + tg);
        if (k > CDIM) k = CDIM;
        if (k < 1) k = 1;
        float ft = __ldg(lrow + tg);
        s_k = k; s_ft = ft; s_at = ft + __ldg(lcn + tg);
    }

    // packed loop constants (hoisted; pure asm is CSE-able)
    const ull LOG2E2  = pk2( 1.44269504f,  1.44269504f);
    const ull NLOG2E2 = pk2(-1.44269504f, -1.44269504f);
    const ull MAGIC2  = pk2( 12582912.0f,  12582912.0f);
    const ull NMAGIC2 = pk2(-12582912.0f, -12582912.0f);
    // poly in g = -f (sign-folded): p = (((C4*g + NC3)*g + C2)*g + NC1)*g + 1
    const ull C4_2 = pk2( 9.6181291076e-3f,  9.6181291076e-3f);
    const ull NC3_2 = pk2(-5.5504108664e-2f, -5.5504108664e-2f);
    const ull C2_2 = pk2( 2.4022650695910071e-1f, 2.4022650695910071e-1f);
    const ull NC1_2 = pk2(-6.9314718055994531e-1f, -6.9314718055994531e-1f);
    const ull ONE2 = pk2(1.0f, 1.0f);

    // ---- pass 1: stream row, packed Z, fused ordered candidate staging ----
    const float4* l4 = (const float4*)lrow;
    const float4* w4 = (const float4*)lcn;

    ull Zp0 = pk2(0.f, 0.f), Zp1 = pk2(0.f, 0.f);
    unsigned pos = wid * WCAP;
    const unsigned lim = wid * WCAP + WCAP;
    for (int j4 = tid; j4 < CV4PAD; j4 += NT) {
        const bool valid = (j4 < CV4);
        float4 L, W;
        if (valid) { L = __ldcs(l4 + j4); W = __ldg(w4 + j4); }
        else {
            L = make_float4(-40.f, -40.f, -40.f, -40.f);   // exp ~ 4e-18, never selected
            W = make_float4(0.f, 0.f, 0.f, 0.f);
        }
        // packed exp accumulation: Z += exp(L + W)
        {
            float a0 = L.x + W.x, a1 = L.y + W.y;
            float a2 = L.z + W.z, a3 = L.w + W.w;
            ull x01 = pk2(a0, a1), x23 = pk2(a2, a3);
            ull t01 = fma2_(x01, LOG2E2, MAGIC2);
            ull t23 = fma2_(x23, LOG2E2, MAGIC2);
            ull r01 = add2_(t01, NMAGIC2);
            ull r23 = add2_(t23, NMAGIC2);
            ull g01 = fma2_(x01, NLOG2E2, r01);     // g = r - x*log2e = -f
            ull g23 = fma2_(x23, NLOG2E2, r23);
            ull p01 = fma2_(C4_2, g01, NC3_2);
            ull p23 = fma2_(C4_2, g23, NC3_2);
            p01 = fma2_(p01, g01, C2_2);  p23 = fma2_(p23, g23, C2_2);
            p01 = fma2_(p01, g01, NC1_2); p23 = fma2_(p23, g23, NC1_2);
            p01 = fma2_(p01, g01, ONE2);  p23 = fma2_(p23, g23, ONE2);
            unsigned e0, e1, e2, e3;
            upk2u(t01, e0, e1); upk2u(t23, e2, e3);
            ull s01 = pk2(__uint_as_float((e0 << 23) + 0x3F800000u),
                          __uint_as_float((e1 << 23) + 0x3F800000u));
            ull s23 = pk2(__uint_as_float((e2 << 23) + 0x3F800000u),
                          __uint_as_float((e3 << 23) + 0x3F800000u));
            Zp0 = fma2_(p01, s01, Zp0);
            Zp1 = fma2_(p23, s23, Zp1);
        }
        // ordered candidate staging (full-warp ballots: loop padded)
        #pragma unroll
        for (int c = 0; c < 4; c++) {
            float f = (c == 0) ? L.x : (c == 1) ? L.y : (c == 2) ? L.z : L.w;
            bool sel = (f >= CUTF);
            unsigned bal = __ballot_sync(0xFFFFFFFFu, sel);
            if (sel) {
                unsigned p = pos + __popc(bal & lmask);
                if (p < lim) {
                    float w = (c == 0) ? W.x : (c == 1) ? W.y : (c == 2) ? W.z : W.w;
                    s_sv[p] = f;
                    s_sa[p] = f + w;
                }
            }
            pos += __popc(bal);
        }
    }
    float z0, z1, z2, z3;
    upk2f(Zp0, z0, z1); upk2f(Zp1, z2, z3);
    float Z = (z0 + z1) + (z2 + z3);
    #pragma unroll
    for (int o = 16; o; o >>= 1) Z += __shfl_xor_sync(0xFFFFFFFFu, Z, o);
    if (lane == 0) { s_red[wid] = Z; s_wcnt[wid] = pos - wid * WCAP; }
    __syncthreads();

    if (tid == 0) {
        float Zt = 0.f;
        unsigned b = 0, mx = 0;
        #pragma unroll
        for (int w = 0; w < NW; w++) {
            Zt += s_red[w];
            unsigned c = s_wcnt[w];
            mx = max(mx, c);
            s_base[w] = b;
            b += c;
        }
        s_Z = Zt; s_n = b; s_cnt = 0u;
        s_fast = ((int)b >= s_k) && (b <= DCAP) && (mx <= WCAP);
    }
    __syncthreads();

    const unsigned n = s_n;
    const int k = s_k;

    if (s_fast) {
        // ---- dense copy ----
        {
            unsigned cw = s_wcnt[wid], b = s_base[wid], src = wid * WCAP;
            for (unsigned i = lane; i < cw; i += 32) {
                s_dv[b + i] = s_sv[src + i];
                s_da[b + i] = s_sa[src + i];
            }
        }
        __syncthreads();

        // ---- warp-0 bisection over smem candidates: exact k-th largest ----
        if (wid == 0) {
            float mx = CUTF;
            for (unsigned i = lane; i < n; i += 32) mx = fmaxf(mx, s_dv[i]);
            #pragma unroll
            for (int o = 16; o; o >>= 1)
                mx = fmaxf(mx, __shfl_xor_sync(0xFFFFFFFFu, mx, o));
            unsigned lo = key_of(CUTF), hi = key_of(mx) + 1u;
            while (hi - lo > 1u) {
                unsigned mid = lo + ((hi - lo) >> 1);
                float mv = val_of(mid);
                int c = 0;
                for (unsigned i = lane; i < n; i += 32) c += (s_dv[i] >= mv);
                c = __reduce_add_sync(0xFFFFFFFFu, c);
                if (c >= k) lo = mid; else hi = mid;
            }
            if (lane == 0) s_T = val_of(lo);
        }
        __syncthreads();

        // ---- masked exp-sum over dense candidates (fixed order) ----
        const float T = s_T;
        float s = 0.f;
        for (unsigned i = tid; i < n; i += NT)
            if (s_dv[i] >= T) s += fexp_(s_da[i]);
        #pragma unroll
        for (int o = 16; o; o >>= 1) s += __shfl_xor_sync(0xFFFFFFFFu, s, o);
        if (lane == 0) s_red[wid] = s;
        __syncthreads();
    } else {
        // ---- exact fallback: block bisection over gmem row (near-unreachable) ----
        unsigned lo = 0u, hi = 0xFFFFFFFFu;
        while (hi - lo > 1u) {
            unsigned mid = lo + ((hi - lo) >> 1);
            float mv = val_of(mid);
            unsigned c = 0;
            for (int j = tid; j < CDIM; j += NT) c += (__ldg(lrow + j) >= mv);
            atomicAdd(&s_cnt, c);
            __syncthreads();
            unsigned ct = s_cnt;
            __syncthreads();
            if (tid == 0) s_cnt = 0u;
            if ((int)ct >= k) lo = mid; else hi = mid;
            __syncthreads();
        }
        if (tid == 0) s_T = val_of(lo);
        __syncthreads();
        const float T = s_T;
        float s = 0.f;
        for (int j = tid; j < CDIM; j += NT) {
            float f = __ldg(lrow + j);
            if (f >= T) s += fexp_(f + __ldg(lcn + j));
        }
        #pragma unroll
        for (int o = 16; o; o >>= 1) s += __shfl_xor_sync(0xFFFFFFFFu, s, o);
        if (lane == 0) s_red[wid] = s;
        __syncthreads();
    }

    // ---- per-row loss, then last-CTA global reduction ----
    if (tid == 0) {
        float S = 0.f;
        #pragma unroll
        for (int w = 0; w < NW; w++) S += s_red[w];
        float Zt = s_Z;
        float T  = s_T;
        float ft = s_ft;
        float at = s_at;
        float pt = (ft >= T) ? (fexp_(at) / Zt) : 0.f;
        float den = S / Zt + 0.01f;                // + 1e-6 * C
        float num = pt + 1e-6f;
        float part = 0.5f * (logf(Zt) - at) + 0.5f * (logf(den) - logf(num));
        g_partial[row] = part;
        __threadfence();
        unsigned t = atomicAdd(&g_done, 1u);
        s_last = (t == BDIM - 1u);
    }
    __syncthreads();

    if (s_last) {
        if (tid == 0) g_done = 0u;
        __threadfence();
        float acc = 0.f;
        #pragma unroll
        for (int i = 0; i < BDIM / 4 / NT; i++) {
            float4 v = ((const float4*)g_partial)[tid + i * NT];
            acc += (v.x + v.y) + (v.z + v.w);
        }
        #pragma unroll
        for (int o = 16; o; o >>= 1) acc += __shfl_xor_sync(0xFFFFFFFFu, acc, o);
        if (lane == 0) s_red[wid] = acc;
        __syncthreads();
        if (tid == 0) {
            float S = 0.f;
            #pragma unroll
            for (int w = 0; w < NW; w++) S += s_red[w];
            out[0] = S * (1.0f / BDIM);
        }
    }
}

extern "C" void kernel_launch(void* const* d_in, const int* in_sizes, int n_in,
                              void* d_out, int out_size) {
    const float* logit  = (const float*)d_in[0];
    const int*   target = (const int*)d_in[1];
    const float* lcn    = (const float*)d_in[2];
    const int*   kpc    = (const int*)d_in[3];
    float* out = (float*)d_out;

    row_kernel<<<BDIM, NT>>>(logit, target, lcn, kpc, out);
}

// round 16
// speedup vs baseline: 1.0097x; 1.0097x over previous
#include <cuda_runtime.h>

#define CDIM 10000
#define CV4  2500
#define CV4PAD 2560   // 10 full iterations of 256 -> no partial-warp collectives
#define BDIM 4096
#define NT   256
#define NW   8
#define WCAP 64      // staging slots per warp
#define DCAP 384     // dense candidate cap
#define CUTF 2.0f

__device__ __align__(16) float g_partial[BDIM];
__device__ unsigned g_done = 0;

__device__ __forceinline__ unsigned key_of(float f) {
    unsigned u = __float_as_uint(f);
    return u ^ ((unsigned)((int)u >> 31) | 0x80000000u);
}
__device__ __forceinline__ float val_of(unsigned k) {
    unsigned m = ((int)k < 0) ? 0x80000000u : 0xFFFFFFFFu;
    return __uint_as_float(k ^ m);
}

// exp(x), pure FFMA + exponent-bit-add, deg-4, valid x in [-80, ~1.9], rel err ~3e-5.
__device__ __forceinline__ float fexp_(float x) {
    const float LOG2E = 1.4426950408889634f;
    float t = fmaf(x, LOG2E, 12582912.0f);        // 1.5*2^23 rounding magic
    float f = fmaf(x, LOG2E, -(t - 12582912.0f)); // f in [-0.5, 0.5]
    float p =          9.6181291076e-3f;
    p = fmaf(p, f, 5.5504108664e-2f);
    p = fmaf(p, f, 2.4022650695910071e-1f);
    p = fmaf(p, f, 6.9314718055994531e-1f);
    p = fmaf(p, f, 1.0f);
    // p in [0.70, 1.42] > 0: scale by 2^ei via integer add into the exponent field
    return __uint_as_float(__float_as_uint(p) + (__float_as_uint(t) << 23));
}

__global__ void __launch_bounds__(NT, 6) row_kernel(
    const float* __restrict__ logit, const int* __restrict__ target,
    const float* __restrict__ lcn,   const int* __restrict__ kpc,
    float* __restrict__ out)
{
    __shared__ float    s_sv[NW * WCAP];   // staged candidate logits (per-warp regions)
    __shared__ float    s_sa[NW * WCAP];   // staged candidate adjusted
    __shared__ float    s_dv[DCAP];        // dense candidate logits
    __shared__ float    s_da[DCAP];        // dense candidate adjusted
    __shared__ float    s_red[NW];
    __shared__ unsigned s_wcnt[NW], s_base[NW];
    __shared__ float    s_Z, s_T, s_ft, s_at;
    __shared__ int      s_k, s_last, s_fast;
    __shared__ unsigned s_n, s_cnt;

    const int row  = blockIdx.x;
    const int tid  = threadIdx.x;
    const int lane = tid & 31;
    const int wid  = tid >> 5;
    const unsigned lmask = (1u << lane) - 1u;

    const float* lrow = logit + (size_t)row * CDIM;

    // early dependent loads (overlap with pass 1 via other warps)
    if (tid == NT - 1) {
        int tg = __ldg(target + row);
        int k  = __ldg(kpc + tg);
        if (k > CDIM) k = CDIM;
        if (k < 1) k = 1;
        float ft = __ldg(lrow + tg);
        s_k = k; s_ft = ft; s_at = ft + __ldg(lcn + tg);
    }

    // ---- pass 1: stream row, Z = sum exp(l+w), guarded ordered candidate staging ----
    const float4* l4 = (const float4*)lrow;
    const float4* w4 = (const float4*)lcn;

    float Z0 = 0.f, Z1 = 0.f;
    unsigned pos = wid * WCAP;
    const unsigned lim = wid * WCAP + WCAP;
    for (int j4 = tid; j4 < CV4PAD; j4 += NT) {
        const bool valid = (j4 < CV4);
        float4 L, W;
        if (valid) { L = __ldcs(l4 + j4); W = __ldg(w4 + j4); }
        else {
            L = make_float4(-40.f, -40.f, -40.f, -40.f);  // exp ~ 4e-18, never selected
            W = make_float4(0.f, 0.f, 0.f, 0.f);
        }
        Z0 += fexp_(L.x + W.x);
        Z1 += fexp_(L.y + W.y);
        Z0 += fexp_(L.z + W.z);
        Z1 += fexp_(L.w + W.w);
        // warp-uniform skip: only enter ballot-compaction when some lane selects.
        // (vote is full-warp: loop is padded so all 32 lanes always participate)
        float mxL = fmaxf(fmaxf(L.x, L.y), fmaxf(L.z, L.w));
        if (__any_sync(0xFFFFFFFFu, mxL >= CUTF)) {
            #pragma unroll
            for (int c = 0; c < 4; c++) {
                float f = (c == 0) ? L.x : (c == 1) ? L.y : (c == 2) ? L.z : L.w;
                bool sel = (f >= CUTF);
                unsigned bal = __ballot_sync(0xFFFFFFFFu, sel);
                if (sel) {
                    unsigned p = pos + __popc(bal & lmask);
                    if (p < lim) {
                        float w = (c == 0) ? W.x : (c == 1) ? W.y : (c == 2) ? W.z : W.w;
                        s_sv[p] = f;
                        s_sa[p] = f + w;
                    }
                }
                pos += __popc(bal);
            }
        }
    }
    float Z = Z0 + Z1;
    #pragma unroll
    for (int o = 16; o; o >>= 1) Z += __shfl_xor_sync(0xFFFFFFFFu, Z, o);
    if (lane == 0) { s_red[wid] = Z; s_wcnt[wid] = pos - wid * WCAP; }
    __syncthreads();

    if (tid == 0) {
        float Zt = 0.f;
        unsigned b = 0, mx = 0;
        #pragma unroll
        for (int w = 0; w < NW; w++) {
            Zt += s_red[w];
            unsigned c = s_wcnt[w];
            mx = max(mx, c);
            s_base[w] = b;
            b += c;
        }
        s_Z = Zt; s_n = b; s_cnt = 0u;
        s_fast = ((int)b >= s_k) && (b <= DCAP) && (mx <= WCAP);
    }
    __syncthreads();

    const unsigned n = s_n;
    const int k = s_k;

    if (s_fast) {
        // ---- dense copy (per-warp regions are contiguous) ----
        {
            unsigned cw = s_wcnt[wid], b = s_base[wid], src = wid * WCAP;
            for (unsigned i = lane; i < cw; i += 32) {
                s_dv[b + i] = s_sv[src + i];
                s_da[b + i] = s_sa[src + i];
            }
        }
        __syncthreads();

        // ---- warp-0 bisection over smem candidates: exact k-th largest ----
        if (wid == 0) {
            float mx = CUTF;
            for (unsigned i = lane; i < n; i += 32) mx = fmaxf(mx, s_dv[i]);
            #pragma unroll
            for (int o = 16; o; o >>= 1)
                mx = fmaxf(mx, __shfl_xor_sync(0xFFFFFFFFu, mx, o));
            unsigned lo = key_of(CUTF), hi = key_of(mx) + 1u;
            while (hi - lo > 1u) {
                unsigned mid = lo + ((hi - lo) >> 1);
                float mv = val_of(mid);
                int c = 0;
                for (unsigned i = lane; i < n; i += 32) c += (s_dv[i] >= mv);
                c = __reduce_add_sync(0xFFFFFFFFu, c);
                if (c >= k) lo = mid; else hi = mid;
            }
            if (lane == 0) s_T = val_of(lo);
        }
        __syncthreads();

        // ---- masked exp-sum over dense candidates (fixed order) ----
        const float T = s_T;
        float s = 0.f;
        for (unsigned i = tid; i < n; i += NT)
            if (s_dv[i] >= T) s += fexp_(s_da[i]);
        #pragma unroll
        for (int o = 16; o; o >>= 1) s += __shfl_xor_sync(0xFFFFFFFFu, s, o);
        if (lane == 0) s_red[wid] = s;
        __syncthreads();
    } else {
        // ---- exact fallback: block bisection over gmem row (near-unreachable) ----
        unsigned lo = 0u, hi = 0xFFFFFFFFu;
        while (hi - lo > 1u) {
            unsigned mid = lo + ((hi - lo) >> 1);
            float mv = val_of(mid);
            unsigned c = 0;
            for (int j = tid; j < CDIM; j += NT) c += (__ldg(lrow + j) >= mv);
            atomicAdd(&s_cnt, c);
            __syncthreads();
            unsigned ct = s_cnt;
            __syncthreads();
            if (tid == 0) s_cnt = 0u;
            if ((int)ct >= k) lo = mid; else hi = mid;
            __syncthreads();
        }
        if (tid == 0) s_T = val_of(lo);
        __syncthreads();
        const float T = s_T;
        float s = 0.f;
        for (int j = tid; j < CDIM; j += NT) {
            float f = __ldg(lrow + j);
            if (f >= T) s += fexp_(f + __ldg(lcn + j));
        }
        #pragma unroll
        for (int o = 16; o; o >>= 1) s += __shfl_xor_sync(0xFFFFFFFFu, s, o);
        if (lane == 0) s_red[wid] = s;
        __syncthreads();
    }

    // ---- per-row loss, then last-CTA global reduction ----
    if (tid == 0) {
        float S = 0.f;
        #pragma unroll
        for (int w = 0; w < NW; w++) S += s_red[w];
        float Zt = s_Z;
        float T  = s_T;
        float ft = s_ft;
        float at = s_at;
        float pt = (ft >= T) ? (fexp_(at) / Zt) : 0.f;
        float den = S / Zt + 0.01f;                // + 1e-6 * C
        float num = pt + 1e-6f;
        float part = 0.5f * (logf(Zt) - at) + 0.5f * (logf(den) - logf(num));
        g_partial[row] = part;
        __threadfence();
        unsigned t = atomicAdd(&g_done, 1u);
        s_last = (t == BDIM - 1u);
    }
    __syncthreads();

    if (s_last) {
        if (tid == 0) g_done = 0u;
        __threadfence();
        float acc = 0.f;
        #pragma unroll
        for (int i = 0; i < BDIM / 4 / NT; i++) {
            float4 v = ((const float4*)g_partial)[tid + i * NT];
            acc += (v.x + v.y) + (v.z + v.w);
        }
        #pragma unroll
        for (int o = 16; o; o >>= 1) acc += __shfl_xor_sync(0xFFFFFFFFu, acc, o);
        if (lane == 0) s_red[wid] = acc;
        __syncthreads();
        if (tid == 0) {
            float S = 0.f;
            #pragma unroll
            for (int w = 0; w < NW; w++) S += s_red[w];
            out[0] = S * (1.0f / BDIM);
        }
    }
}

extern "C" void kernel_launch(void* const* d_in, const int* in_sizes, int n_in,
                              void* d_out, int out_size) {
    const float* logit  = (const float*)d_in[0];
    const int*   target = (const int*)d_in[1];
    const float* lcn    = (const float*)d_in[2];
    const int*   kpc    = (const int*)d_in[3];
    float* out = (float*)d_out;

    row_kernel<<<BDIM, NT>>>(logit, target, lcn, kpc, out);
}

// round 17
// speedup vs baseline: 1.1328x; 1.1219x over previous
#include <cuda_runtime.h>

#define CDIM 10000
#define CV4  2500
#define BDIM 4096
#define NT   256
#define NW   8
#define WCAP 64      // staging slots per warp
#define DCAP 384     // dense candidate cap
#define CUTF 2.0f

__device__ __align__(16) float g_partial[BDIM];
__device__ unsigned g_done = 0;

__device__ __forceinline__ unsigned key_of(float f) {
    unsigned u = __float_as_uint(f);
    return u ^ ((unsigned)((int)u >> 31) | 0x80000000u);
}
__device__ __forceinline__ float val_of(unsigned k) {
    unsigned m = ((int)k < 0) ? 0x80000000u : 0xFFFFFFFFu;
    return __uint_as_float(k ^ m);
}

// exp(x), pure FFMA + exponent-bit-add, deg-4, valid x in [-110, ~1.9], rel err ~3e-5.
__device__ __forceinline__ float fexp_(float x) {
    const float LOG2E = 1.4426950408889634f;
    float t = fmaf(x, LOG2E, 12582912.0f);        // 1.5*2^23 rounding magic
    float f = fmaf(x, LOG2E, -(t - 12582912.0f)); // f in [-0.5, 0.5]
    float p =          9.6181291076e-3f;
    p = fmaf(p, f, 5.5504108664e-2f);
    p = fmaf(p, f, 2.4022650695910071e-1f);
    p = fmaf(p, f, 6.9314718055994531e-1f);
    p = fmaf(p, f, 1.0f);
    // p in [0.70, 1.42] > 0: scale by 2^e via integer add into the exponent field
    return __uint_as_float(__float_as_uint(p) + (__float_as_uint(t) << 23));
}

// per-float4 hot-loop body: Z accumulation + unconditional ordered ballot staging
__device__ __forceinline__ void body_(
    const float4& L, const float4& W, float& Z0, float& Z1,
    unsigned& pos, unsigned lim, unsigned lmask, float* s_sv, float* s_sa)
{
    Z0 += fexp_(L.x + W.x);
    Z1 += fexp_(L.y + W.y);
    Z0 += fexp_(L.z + W.z);
    Z1 += fexp_(L.w + W.w);
    #pragma unroll
    for (int c = 0; c < 4; c++) {
        float f = (c == 0) ? L.x : (c == 1) ? L.y : (c == 2) ? L.z : L.w;
        bool sel = (f >= CUTF);
        unsigned bal = __ballot_sync(0xFFFFFFFFu, sel);
        if (sel) {
            unsigned p = pos + __popc(bal & lmask);
            if (p < lim) {
                float w = (c == 0) ? W.x : (c == 1) ? W.y : (c == 2) ? W.z : W.w;
                s_sv[p] = f;
                s_sa[p] = f + w;
            }
        }
        pos += __popc(bal);
    }
}

__global__ void __launch_bounds__(NT, 6) row_kernel(
    const float* __restrict__ logit, const int* __restrict__ target,
    const float* __restrict__ lcn,   const int* __restrict__ kpc,
    float* __restrict__ out)
{
    __shared__ float    s_sv[NW * WCAP];   // staged candidate logits (per-warp regions)
    __shared__ float    s_sa[NW * WCAP];   // staged candidate adjusted
    __shared__ float    s_dv[DCAP];        // dense candidate logits
    __shared__ float    s_da[DCAP];        // dense candidate adjusted
    __shared__ float    s_red[NW];
    __shared__ unsigned s_wcnt[NW], s_base[NW];
    __shared__ float    s_Z, s_T, s_ft, s_at;
    __shared__ int      s_k, s_last, s_fast;
    __shared__ unsigned s_n, s_cnt;

    const int row  = blockIdx.x;
    const int tid  = threadIdx.x;
    const int lane = tid & 31;
    const int wid  = tid >> 5;
    const unsigned lmask = (1u << lane) - 1u;

    const float* lrow = logit + (size_t)row * CDIM;

    // early dependent loads (overlap with pass 1 via other warps)
    if (tid == NT - 1) {
        int tg = __ldg(target + row);
        int k  = __ldg(kpc + tg);
        if (k > CDIM) k = CDIM;
        if (k < 1) k = 1;
        float ft = __ldg(lrow + tg);
        s_k = k; s_ft = ft; s_at = ft + __ldg(lcn + tg);
    }

    // ---- pass 1: 10 statically-known iterations; 0..8 always valid, 9 predicated.
    //      Unrolled in pairs with all 4 loads issued before consumption (2x MLP).
    //      No data-dependent branches anywhere in the steady-state loop.
    const float4* l4 = (const float4*)lrow;
    const float4* w4 = (const float4*)lcn;

    float Z0 = 0.f, Z1 = 0.f;
    unsigned pos = wid * WCAP;
    const unsigned lim = wid * WCAP + WCAP;

    #pragma unroll
    for (int i = 0; i < 4; i++) {
        const int ja = tid + (2 * i) * NT;
        const int jb = ja + NT;
        float4 La = __ldcs(l4 + ja);
        float4 Wa = __ldg(w4 + ja);
        float4 Lb = __ldcs(l4 + jb);
        float4 Wb = __ldg(w4 + jb);
        body_(La, Wa, Z0, Z1, pos, lim, lmask, s_sv, s_sa);
        body_(Lb, Wb, Z0, Z1, pos, lim, lmask, s_sv, s_sa);
    }
    {   // tail pair: iter 8 always valid, iter 9 predicated (sentinel keeps ballots full-warp)
        const int ja = tid + 8 * NT;
        const int jb = tid + 9 * NT;
        const bool vb = (jb < CV4);
        float4 La = __ldcs(l4 + ja);
        float4 Wa = __ldg(w4 + ja);
        float4 Lb = make_float4(-40.f, -40.f, -40.f, -40.f);  // exp ~ 4e-18, never selected
        float4 Wb = make_float4(0.f, 0.f, 0.f, 0.f);
        if (vb) { Lb = __ldcs(l4 + jb); Wb = __ldg(w4 + jb); }
        body_(La, Wa, Z0, Z1, pos, lim, lmask, s_sv, s_sa);
        body_(Lb, Wb, Z0, Z1, pos, lim, lmask, s_sv, s_sa);
    }

    float Z = Z0 + Z1;
    #pragma unroll
    for (int o = 16; o; o >>= 1) Z += __shfl_xor_sync(0xFFFFFFFFu, Z, o);
    if (lane == 0) { s_red[wid] = Z; s_wcnt[wid] = pos - wid * WCAP; }
    __syncthreads();

    if (tid == 0) {
        float Zt = 0.f;
        unsigned b = 0, mx = 0;
        #pragma unroll
        for (int w = 0; w < NW; w++) {
            Zt += s_red[w];
            unsigned c = s_wcnt[w];
            mx = max(mx, c);
            s_base[w] = b;
            b += c;
        }
        s_Z = Zt; s_n = b; s_cnt = 0u;
        s_fast = ((int)b >= s_k) && (b <= DCAP) && (mx <= WCAP);
    }
    __syncthreads();

    const unsigned n = s_n;
    const int k = s_k;

    if (s_fast) {
        // ---- dense copy (per-warp regions are contiguous) ----
        {
            unsigned cw = s_wcnt[wid], b = s_base[wid], src = wid * WCAP;
            for (unsigned i = lane; i < cw; i += 32) {
                s_dv[b + i] = s_sv[src + i];
                s_da[b + i] = s_sa[src + i];
            }
        }
        __syncthreads();

        // ---- warp-0 bisection over smem candidates: exact k-th largest ----
        if (wid == 0) {
            float mx = CUTF;
            for (unsigned i = lane; i < n; i += 32) mx = fmaxf(mx, s_dv[i]);
            #pragma unroll
            for (int o = 16; o; o >>= 1)
                mx = fmaxf(mx, __shfl_xor_sync(0xFFFFFFFFu, mx, o));
            unsigned lo = key_of(CUTF), hi = key_of(mx) + 1u;
            while (hi - lo > 1u) {
                unsigned mid = lo + ((hi - lo) >> 1);
                float mv = val_of(mid);
                int c = 0;
                for (unsigned i = lane; i < n; i += 32) c += (s_dv[i] >= mv);
                c = __reduce_add_sync(0xFFFFFFFFu, c);
                if (c >= k) lo = mid; else hi = mid;
            }
            if (lane == 0) s_T = val_of(lo);
        }
        __syncthreads();

        // ---- masked exp-sum over dense candidates (fixed order) ----
        const float T = s_T;
        float s = 0.f;
        for (unsigned i = tid; i < n; i += NT)
            if (s_dv[i] >= T) s += fexp_(s_da[i]);
        #pragma unroll
        for (int o = 16; o; o >>= 1) s += __shfl_xor_sync(0xFFFFFFFFu, s, o);
        if (lane == 0) s_red[wid] = s;
        __syncthreads();
    } else {
        // ---- exact fallback: block bisection over gmem row (near-unreachable) ----
        unsigned lo = 0u, hi = 0xFFFFFFFFu;
        while (hi - lo > 1u) {
            unsigned mid = lo + ((hi - lo) >> 1);
            float mv = val_of(mid);
            unsigned c = 0;
            for (int j = tid; j < CDIM; j += NT) c += (__ldg(lrow + j) >= mv);
            atomicAdd(&s_cnt, c);
            __syncthreads();
            unsigned ct = s_cnt;
            __syncthreads();
            if (tid == 0) s_cnt = 0u;
            if ((int)ct >= k) lo = mid; else hi = mid;
            __syncthreads();
        }
        if (tid == 0) s_T = val_of(lo);
        __syncthreads();
        const float T = s_T;
        float s = 0.f;
        for (int j = tid; j < CDIM; j += NT) {
            float f = __ldg(lrow + j);
            if (f >= T) s += fexp_(f + __ldg(lcn + j));
        }
        #pragma unroll
        for (int o = 16; o; o >>= 1) s += __shfl_xor_sync(0xFFFFFFFFu, s, o);
        if (lane == 0) s_red[wid] = s;
        __syncthreads();
    }

    // ---- per-row loss, then last-CTA global reduction ----
    if (tid == 0) {
        float S = 0.f;
        #pragma unroll
        for (int w = 0; w < NW; w++) S += s_red[w];
        float Zt = s_Z;
        float T  = s_T;
        float ft = s_ft;
        float at = s_at;
        float pt = (ft >= T) ? (fexp_(at) / Zt) : 0.f;
        float den = S / Zt + 0.01f;                // + 1e-6 * C
        float num = pt + 1e-6f;
        float part = 0.5f * (logf(Zt) - at) + 0.5f * (logf(den) - logf(num));
        g_partial[row] = part;
        __threadfence();
        unsigned t = atomicAdd(&g_done, 1u);
        s_last = (t == BDIM - 1u);
    }
    __syncthreads();

    if (s_last) {
        if (tid == 0) g_done = 0u;
        __threadfence();
        float acc = 0.f;
        #pragma unroll
        for (int i = 0; i < BDIM / 4 / NT; i++) {
            float4 v = ((const float4*)g_partial)[tid + i * NT];
            acc += (v.x + v.y) + (v.z + v.w);
        }
        #pragma unroll
        for (int o = 16; o; o >>= 1) acc += __shfl_xor_sync(0xFFFFFFFFu, acc, o);
        if (lane == 0) s_red[wid] = acc;
        __syncthreads();
        if (tid == 0) {
            float S = 0.f;
            #pragma unroll
            for (int w = 0; w < NW; w++) S += s_red[w];
            out[0] = S * (1.0f / BDIM);
        }
    }
}

extern "C" void kernel_launch(void* const* d_in, const int* in_sizes, int n_in,
                              void* d_out, int out_size) {
    const float* logit  = (const float*)d_in[0];
    const int*   target = (const int*)d_in[1];
    const float* lcn    = (const float*)d_in[2];
    const int*   kpc    = (const int*)d_in[3];
    float* out = (float*)d_out;

    row_kernel<<<BDIM, NT>>>(logit, target, lcn, kpc, out);
}